// round 6
// baseline (speedup 1.0000x reference)
#include <cuda_runtime.h>
#include <cuda_bf16.h>

// TimeFeatureEmbedding: y = x @ W^T + b  ([B,T,4] x [512,4] -> [B,T,512]),
// broadcast each (b,t) row S times -> [B,T,S,512].  402.7 MB pure store stream.
//
// Persistent flat decomposition: grid = 1216 CTAs (152 SMs x occ 8), each CTA
// owns ONE contiguous chunk of the flat float4 output space -> single wave,
// no wave-quantization tail. Chunks and row boundaries are both multiples of
// the CTA stride (256 float4), so each thread's D-slice (tid & 127) is fixed:
// W and b load once; only x4 + 16 FMAs recompute at row-segment boundaries.

#define TFE_GRID 1216   // 152 SMs * 8 CTAs

__global__ __launch_bounds__(256, 8)
void tfe_broadcast_kernel(const float* __restrict__ x,
                          const float* __restrict__ W,
                          const float* __restrict__ b,
                          float* __restrict__ out,
                          int S, int n4, int chunk)
{
    const int tid = threadIdx.x;
    const int d4  = tid & 127;            // float4 index within D_MODEL=512

    // Hoisted loads: bias slice + 4 W rows for this thread's D-slice.
    const float4 b4 = __ldg(reinterpret_cast<const float4*>(b) + d4);
    const float4* W4 = reinterpret_cast<const float4*>(W);
    const float4 w0 = __ldg(W4 + d4 * 4 + 0);
    const float4 w1 = __ldg(W4 + d4 * 4 + 1);
    const float4 w2 = __ldg(W4 + d4 * 4 + 2);
    const float4 w3 = __ldg(W4 + d4 * 4 + 3);

    const int row4 = S * 128;             // float4 per (b,t) row (multiple of 256)

    int i   = blockIdx.x * chunk;         // chunk is a multiple of 256
    int end = i + chunk;
    if (end > n4) end = n4;

    float4* __restrict__ out4 = reinterpret_cast<float4*>(out);

    while (i < end) {
        const int bt = i / row4;                  // current (b,t) row
        int seg_end = (bt + 1) * row4;            // row boundary (mult of 256)
        if (seg_end > end) seg_end = end;

        // recompute y for this row: one 16B broadcast load + 16 FMA
        const float4 x4 = __ldg(reinterpret_cast<const float4*>(x) + bt);
        float4 y4;
        y4.x = fmaf(x4.x, w0.x, fmaf(x4.y, w0.y, fmaf(x4.z, w0.z, fmaf(x4.w, w0.w, b4.x))));
        y4.y = fmaf(x4.x, w1.x, fmaf(x4.y, w1.y, fmaf(x4.z, w1.z, fmaf(x4.w, w1.w, b4.y))));
        y4.z = fmaf(x4.x, w2.x, fmaf(x4.y, w2.y, fmaf(x4.z, w2.z, fmaf(x4.w, w2.w, b4.z))));
        y4.w = fmaf(x4.x, w3.x, fmaf(x4.y, w3.y, fmaf(x4.z, w3.z, fmaf(x4.w, w3.w, b4.w))));

        // i and seg_end are multiples of 256 -> (j & 127) == d4 always:
        // same register value streamed, warp writes 512B contiguous per STG.
        #pragma unroll 4
        for (int j = i + tid; j < seg_end; j += 256) {
            __stcs(out4 + j, y4);   // evict-first streaming store
        }
        i = seg_end;
    }
}

extern "C" void kernel_launch(void* const* d_in, const int* in_sizes, int n_in,
                              void* d_out, int out_size)
{
    // Inputs: x [B,T,4] f32, S (scalar), W [512,4] f32, b [512] f32.
    const float* x = (const float*)d_in[0];
    const float* W = (const float*)d_in[2];
    const float* b = (const float*)d_in[3];
    float* out = (float*)d_out;

    const int BT = in_sizes[0] / 4;          // B*T rows (d_inp = 4)
    const int S  = out_size / (BT * 512);    // recover S arithmetically
    const int n4 = BT * S * 128;             // total float4 stores

    // Per-CTA chunk, rounded up to a multiple of the CTA stride (256 float4)
    int chunk = (n4 + TFE_GRID - 1) / TFE_GRID;
    chunk = ((chunk + 255) / 256) * 256;
    int grid = (n4 + chunk - 1) / chunk;     // <= TFE_GRID

    tfe_broadcast_kernel<<<grid, 256>>>(x, W, b, out, S, n4, chunk);
}

// round 7
// speedup vs baseline: 1.1374x; 1.1374x over previous
#include <cuda_runtime.h>
#include <cuda_bf16.h>

// TimeFeatureEmbedding: y = x @ W^T + b  ([B,T,4] x [512,4] -> [B,T,512]),
// broadcast each (b,t) row S times -> [B,T,S,512].  402.7 MB pure store stream.
//
// R2 (1 CTA/row, grid 3072): 61.5us, DRAM 73.6%. R5 persistent: REGRESSED
// (no work-stealing -> straggler-bound). This round: keep short CTAs, split
// each row into `split` parts -> grid 6144, ~5 waves, tail quantization
// ~0.05 wave instead of 0.53. Each CTA: 16 x STG.128 per thread of one
// register-resident float4 (d-slice fixed by tid & 127 since all strides
// are multiples of 256 float4).

__global__ __launch_bounds__(256, 8)
void tfe_broadcast_kernel(const float* __restrict__ x,
                          const float* __restrict__ W,
                          const float* __restrict__ b,
                          float* __restrict__ out,
                          int S, int split)
{
    const int bt   = blockIdx.x / split;     // which (b,t) row
    const int part = blockIdx.x % split;     // which slice of the S repeats
    const int tid  = threadIdx.x;
    const int d4   = tid & 127;              // float4 index within D_MODEL=512

    // x row: 4 floats broadcast across the CTA (L1/L2-hot after wave 1)
    const float4 x4 = __ldg(reinterpret_cast<const float4*>(x) + bt);

    // bias + W slice for this thread's 4 output dims
    const float4 b4 = __ldg(reinterpret_cast<const float4*>(b) + d4);
    const float4* W4 = reinterpret_cast<const float4*>(W);
    const float4 w0 = __ldg(W4 + d4 * 4 + 0);
    const float4 w1 = __ldg(W4 + d4 * 4 + 1);
    const float4 w2 = __ldg(W4 + d4 * 4 + 2);
    const float4 w3 = __ldg(W4 + d4 * 4 + 3);

    float4 y4;
    y4.x = fmaf(x4.x, w0.x, fmaf(x4.y, w0.y, fmaf(x4.z, w0.z, fmaf(x4.w, w0.w, b4.x))));
    y4.y = fmaf(x4.x, w1.x, fmaf(x4.y, w1.y, fmaf(x4.z, w1.z, fmaf(x4.w, w1.w, b4.y))));
    y4.z = fmaf(x4.x, w2.x, fmaf(x4.y, w2.y, fmaf(x4.z, w2.z, fmaf(x4.w, w2.w, b4.z))));
    y4.w = fmaf(x4.x, w3.x, fmaf(x4.y, w3.y, fmaf(x4.z, w3.z, fmaf(x4.w, w3.w, b4.w))));

    // This CTA's slice: (S/split)*128 float4, contiguous, 256-aligned start
    // (S/split rows of 128 float4 each; 128*(S/split) is a multiple of 256
    // whenever S/split is even — guaranteed by the launcher's split choice).
    const int slice4 = (S / split) * 128;
    float4* out4 = reinterpret_cast<float4*>(out)
                 + (size_t)bt * (size_t)S * 128u
                 + (size_t)part * (size_t)slice4;

    #pragma unroll 4
    for (int i = tid; i < slice4; i += 256) {
        __stcs(out4 + i, y4);   // evict-first streaming store
    }
}

extern "C" void kernel_launch(void* const* d_in, const int* in_sizes, int n_in,
                              void* d_out, int out_size)
{
    // Inputs: x [B,T,4] f32, S (scalar), W [512,4] f32, b [512] f32.
    const float* x = (const float*)d_in[0];
    const float* W = (const float*)d_in[2];
    const float* b = (const float*)d_in[3];
    float* out = (float*)d_out;

    const int BT = in_sizes[0] / 4;          // B*T rows (d_inp = 4)
    const int S  = out_size / (BT * 512);    // recover S arithmetically

    // Split each row in 2 if the per-part repeat count stays even (keeps the
    // 256-float4 alignment invariant); otherwise 1 CTA per row (R2 behavior).
    const int split = ((S % 4) == 0) ? 2 : 1;

    tfe_broadcast_kernel<<<BT * split, 256>>>(x, W, b, out, S, split);
}

// round 8
// speedup vs baseline: 1.1776x; 1.0354x over previous
#include <cuda_runtime.h>
#include <cuda_bf16.h>

// TimeFeatureEmbedding: y = x @ W^T + b  ([B,T,4] x [512,4] -> [B,T,512]),
// broadcast each (b,t) row S times -> [B,T,S,512].  402.7 MB pure store stream.
//
// History: R2 1-CTA/row 61.5us; R5 persistent REGRESSED (straggler-bound);
// R6 split=2 59.9us (tail-granularity win). This round: split=4 -> grid
// 12288, 8 STG.128/thread, drain quantization halves again. All slice
// bases/lengths remain multiples of the 256-float4 CTA stride, so each
// thread's D-slice (tid & 127) is a single register-resident float4 and
// every warp store is 512B contiguous.

__global__ __launch_bounds__(256, 8)
void tfe_broadcast_kernel(const float* __restrict__ x,
                          const float* __restrict__ W,
                          const float* __restrict__ b,
                          float* __restrict__ out,
                          int S, int split)
{
    const int bt   = blockIdx.x / split;     // which (b,t) row
    const int part = blockIdx.x % split;     // which slice of the S repeats
    const int tid  = threadIdx.x;
    const int d4   = tid & 127;              // float4 index within D_MODEL=512

    // x row: 4 floats broadcast across the CTA (L2-hot after first touch)
    const float4 x4 = __ldg(reinterpret_cast<const float4*>(x) + bt);

    // bias + W slice for this thread's 4 output dims
    const float4 b4 = __ldg(reinterpret_cast<const float4*>(b) + d4);
    const float4* W4 = reinterpret_cast<const float4*>(W);
    const float4 w0 = __ldg(W4 + d4 * 4 + 0);
    const float4 w1 = __ldg(W4 + d4 * 4 + 1);
    const float4 w2 = __ldg(W4 + d4 * 4 + 2);
    const float4 w3 = __ldg(W4 + d4 * 4 + 3);

    float4 y4;
    y4.x = fmaf(x4.x, w0.x, fmaf(x4.y, w0.y, fmaf(x4.z, w0.z, fmaf(x4.w, w0.w, b4.x))));
    y4.y = fmaf(x4.x, w1.x, fmaf(x4.y, w1.y, fmaf(x4.z, w1.z, fmaf(x4.w, w1.w, b4.y))));
    y4.z = fmaf(x4.x, w2.x, fmaf(x4.y, w2.y, fmaf(x4.z, w2.z, fmaf(x4.w, w2.w, b4.z))));
    y4.w = fmaf(x4.x, w3.x, fmaf(x4.y, w3.y, fmaf(x4.z, w3.z, fmaf(x4.w, w3.w, b4.w))));

    // Slice: (S/split)*128 float4, contiguous, 256-aligned start. The
    // launcher guarantees S/split is even -> slice length is a multiple of
    // 256 -> (i & 127) == d4 on every iteration: one register streamed,
    // warps write 512B contiguous per STG.
    const int slice4 = (S / split) * 128;
    float4* out4 = reinterpret_cast<float4*>(out)
                 + (size_t)bt * (size_t)S * 128u
                 + (size_t)part * (size_t)slice4;

    #pragma unroll 4
    for (int i = tid; i < slice4; i += 256) {
        __stcs(out4 + i, y4);   // evict-first streaming store
    }
}

extern "C" void kernel_launch(void* const* d_in, const int* in_sizes, int n_in,
                              void* d_out, int out_size)
{
    // Inputs: x [B,T,4] f32, S (scalar), W [512,4] f32, b [512] f32.
    const float* x = (const float*)d_in[0];
    const float* W = (const float*)d_in[2];
    const float* b = (const float*)d_in[3];
    float* out = (float*)d_out;

    const int BT = in_sizes[0] / 4;          // B*T rows (d_inp = 4)
    const int S  = out_size / (BT * 512);    // recover S arithmetically

    // Largest split in {4,2,1} with S/split even (preserves the 256-float4
    // alignment invariant). S=64 -> split=4, grid=12288, 8 stores/thread.
    int split = 1;
    if ((S % 8) == 0)      split = 4;
    else if ((S % 4) == 0) split = 2;

    tfe_broadcast_kernel<<<BT * split, 256>>>(x, W, b, out, S, split);
}